// round 3
// baseline (speedup 1.0000x reference)
#include <cuda_runtime.h>
#include <math.h>

// rbfLayer, round 3: two-kernel split.
// K1 (edge-parallel): per-edge geometry -> index-space coords (s_r, s_a),
//     stored in a __device__ float2 scratch (12.8MB, L2-resident).
// K2 (point-parallel): 4 lanes/point, lane t owns feature pair j={2t,2t+1}.
//     Z_p[nm] (f32x2) accumulated over 16 edges with PoU hat-weight decode,
//     then contracted against shared-mem K (float4/LDS.128 layout).

#define PTS_PER_BLOCK 32
#define BLOCK_THREADS 128
#define MAX_EDGES 1600000

typedef unsigned long long u64;

__device__ float2 g_edge_w[MAX_EDGES];   // (s_r, s_a) per edge

__device__ __forceinline__ u64 pack2(float lo, float hi) {
    u64 r;
    asm("mov.b64 %0, {%1,%2};" : "=l"(r)
        : "r"(__float_as_int(lo)), "r"(__float_as_int(hi)));
    return r;
}
__device__ __forceinline__ void unpack2(u64 v, float& lo, float& hi) {
    int a, b;
    asm("mov.b64 {%0,%1}, %2;" : "=r"(a), "=r"(b) : "l"(v));
    lo = __int_as_float(a); hi = __int_as_float(b);
}
__device__ __forceinline__ u64 fma2(u64 a, u64 b, u64 c) {
    u64 d;
    asm("fma.rn.f32x2 %0, %1, %2, %3;" : "=l"(d) : "l"(a), "l"(b), "l"(c));
    return d;
}
__device__ __forceinline__ u64 mul2(u64 a, u64 b) {
    u64 d;
    asm("mul.rn.f32x2 %0, %1, %2;" : "=l"(d) : "l"(a), "l"(b));
    return d;
}

// ---------------- Kernel 1: per-edge geometry ----------------
__global__ __launch_bounds__(256)
void geom_kernel(const float2* __restrict__ pos,
                 const int*    __restrict__ nbrs,
                 int n_edges)
{
    int e = blockIdx.x * 256 + threadIdx.x;
    if (e >= n_edges) return;

    int nb = __ldg(nbrs + e);
    float2 q = __ldg(&pos[nb]);
    float2 p = __ldg(&pos[e >> 4]);          // uniform DEG=16 (setup-guaranteed)
    float dx = q.x - p.x, dy = q.y - p.y;

    float d2 = fmaxf(fmaf(dx, dx, dy * dy), 1e-24f);
    float rinv = rsqrtf(d2);
    float nrm = d2 * rinv;
    float sr = nrm * 1.5f;                   // radial index-space, [0,3)

    // atan2 via octant fold + minimax poly (err ~1e-5 rad)
    float ax = fabsf(dx), ay = fabsf(dy);
    float mn = fminf(ax, ay);
    float mx = fmaxf(fmaxf(ax, ay), 1e-30f);
    float tq = __fdividef(mn, mx);
    float t2 = tq * tq;
    float pl = -0.0117212f;
    pl = fmaf(pl, t2, 0.05265332f);
    pl = fmaf(pl, t2, -0.11643287f);
    pl = fmaf(pl, t2, 0.19354346f);
    pl = fmaf(pl, t2, -0.33262347f);
    pl = fmaf(pl, t2, 0.99997726f);
    float ang = pl * tq;
    if (ay > ax) ang = 1.5707963267948966f - ang;
    if (dx < 0.0f) ang = 3.141592653589793f - ang;
    float th = ang * 0.3183098861837907f;
    th = (dy < 0.0f) ? -th : th;             // [-1,1]
    float sa = fmaf(th, 2.0f, 2.0f);         // angular index-space, [0,4]

    g_edge_w[e] = make_float2(sr, sa);
}

// ---------------- Kernel 2: accumulate + contract ----------------
__device__ __forceinline__ void accum_edge(float sr, float sa, u64 fv2,
                                           u64 Zp[16]) {
    int   kr = (int)sr;
    float fr = sr - (float)kr;
    int   ka = (int)sa;
    float fa = sa - (float)ka;
    int   k0 = ka & 3;
    int   k1 = (ka + 1) & 3;

    float wa0 = (k0 == 0) ? (1.0f - fa) : ((k1 == 0) ? fa : 0.0f);
    float wa1 = (k0 == 1) ? (1.0f - fa) : ((k1 == 1) ? fa : 0.0f);
    float wa2 = (k0 == 2) ? (1.0f - fa) : ((k1 == 2) ? fa : 0.0f);
    float wa3 = (k0 == 3) ? (1.0f - fa) : ((k1 == 3) ? fa : 0.0f);

    float wr0 = (kr == 0) ? (1.0f - fr) : 0.0f;
    float wr1 = (kr == 1) ? (1.0f - fr) : ((kr == 0) ? fr : 0.0f);
    float wr2 = (kr == 2) ? (1.0f - fr) : ((kr == 1) ? fr : 0.0f);
    float wr3 = (kr == 2) ? fr : 0.0f;

    u64 t0 = mul2(pack2(wa0, wa0), fv2);
    u64 t1 = mul2(pack2(wa1, wa1), fv2);
    u64 t2 = mul2(pack2(wa2, wa2), fv2);
    u64 t3 = mul2(pack2(wa3, wa3), fv2);
    u64 r0 = pack2(wr0, wr0);
    u64 r1 = pack2(wr1, wr1);
    u64 r2 = pack2(wr2, wr2);
    u64 r3 = pack2(wr3, wr3);

    Zp[0]  = fma2(r0, t0, Zp[0]);   Zp[1]  = fma2(r0, t1, Zp[1]);
    Zp[2]  = fma2(r0, t2, Zp[2]);   Zp[3]  = fma2(r0, t3, Zp[3]);
    Zp[4]  = fma2(r1, t0, Zp[4]);   Zp[5]  = fma2(r1, t1, Zp[5]);
    Zp[6]  = fma2(r1, t2, Zp[6]);   Zp[7]  = fma2(r1, t3, Zp[7]);
    Zp[8]  = fma2(r2, t0, Zp[8]);   Zp[9]  = fma2(r2, t1, Zp[9]);
    Zp[10] = fma2(r2, t2, Zp[10]);  Zp[11] = fma2(r2, t3, Zp[11]);
    Zp[12] = fma2(r3, t0, Zp[12]);  Zp[13] = fma2(r3, t1, Zp[13]);
    Zp[14] = fma2(r3, t2, Zp[14]);  Zp[15] = fma2(r3, t3, Zp[15]);
}

__global__ __launch_bounds__(BLOCK_THREADS, 8)
void rbf_layer_kernel(const float* __restrict__ feat,
                      const float* __restrict__ kern,   // [8][8][4][4]
                      const int*   __restrict__ nbrs,
                      const int*   __restrict__ rsp,
                      float*       __restrict__ out,
                      int n_pts)
{
    // skp4[(i*8+nm2)*4 + t] = {K[i][2t][2nm2], K[i][2t+1][2nm2],
    //                          K[i][2t][2nm2+1], K[i][2t+1][2nm2+1]}
    __shared__ float4 skp4[8 * 8 * 4];     // 4 KB
    for (int idx = threadIdx.x; idx < 256; idx += BLOCK_THREADS) {
        int tt  = idx & 3;
        int nm2 = (idx >> 2) & 7;
        int i   = idx >> 5;
        int n0 = 2 * nm2, n1 = 2 * nm2 + 1;
        skp4[idx] = make_float4(kern[(i * 8 + 2 * tt)     * 16 + n0],
                                kern[(i * 8 + 2 * tt + 1) * 16 + n0],
                                kern[(i * 8 + 2 * tt)     * 16 + n1],
                                kern[(i * 8 + 2 * tt + 1) * 16 + n1]);
    }
    __syncthreads();

    int gid   = blockIdx.x * BLOCK_THREADS + threadIdx.x;
    int point = gid >> 2;
    int t     = threadIdx.x & 3;

    bool valid = (point < n_pts);
    int pclamp = valid ? point : 0;

    const float2* f2 = (const float2*)feat;

    int beg = valid ? rsp[pclamp]     : 0;
    int end = valid ? rsp[pclamp + 1] : 0;
    int cnt = end - beg;

    u64 Zp[16];
    #pragma unroll
    for (int k = 0; k < 16; ++k) Zp[k] = 0ull;

    if (cnt == 16) {
        #pragma unroll
        for (int g = 0; g < 4; ++g) {
            int e = beg + g * 4;
            // batch independent loads (MLP): nbrs, weights, then features
            int nb0 = __ldg(nbrs + e + 0);
            int nb1 = __ldg(nbrs + e + 1);
            int nb2 = __ldg(nbrs + e + 2);
            int nb3 = __ldg(nbrs + e + 3);
            float2 w0 = __ldg(&g_edge_w[e + 0]);
            float2 w1 = __ldg(&g_edge_w[e + 1]);
            float2 w2 = __ldg(&g_edge_w[e + 2]);
            float2 w3 = __ldg(&g_edge_w[e + 3]);
            float2 fv0 = __ldg(&f2[nb0 * 4 + t]);
            float2 fv1 = __ldg(&f2[nb1 * 4 + t]);
            float2 fv2v = __ldg(&f2[nb2 * 4 + t]);
            float2 fv3 = __ldg(&f2[nb3 * 4 + t]);
            accum_edge(w0.x, w0.y, pack2(fv0.x, fv0.y), Zp);
            accum_edge(w1.x, w1.y, pack2(fv1.x, fv1.y), Zp);
            accum_edge(w2.x, w2.y, pack2(fv2v.x, fv2v.y), Zp);
            accum_edge(w3.x, w3.y, pack2(fv3.x, fv3.y), Zp);
        }
    } else {
        for (int e = beg; e < end; ++e) {
            int nb = __ldg(nbrs + e);
            float2 w = __ldg(&g_edge_w[e]);
            float2 fv = __ldg(&f2[nb * 4 + t]);
            accum_edge(w.x, w.y, pack2(fv.x, fv.y), Zp);
        }
    }

    // Epilogue: pr[i] = sum_nm <K[i][jpair_t][nm], Zp[nm]>  (f32x2), then hadd
    float pr[8];
    #pragma unroll
    for (int i = 0; i < 8; ++i) {
        u64 acc = 0ull;
        #pragma unroll
        for (int nm2 = 0; nm2 < 8; ++nm2) {
            float4 kk = skp4[(i * 8 + nm2) * 4 + t];
            acc = fma2(pack2(kk.x, kk.y), Zp[2 * nm2],     acc);
            acc = fma2(pack2(kk.z, kk.w), Zp[2 * nm2 + 1], acc);
        }
        float lo, hi;
        unpack2(acc, lo, hi);
        pr[i] = lo + hi;
    }

    #pragma unroll
    for (int i = 0; i < 8; ++i) {
        pr[i] += __shfl_xor_sync(0xffffffffu, pr[i], 1);
        pr[i] += __shfl_xor_sync(0xffffffffu, pr[i], 2);
    }

    if (valid) {
        float o0 = pr[0], o1 = pr[4];
        if (t == 1) { o0 = pr[1]; o1 = pr[5]; }
        if (t == 2) { o0 = pr[2]; o1 = pr[6]; }
        if (t == 3) { o0 = pr[3]; o1 = pr[7]; }
        out[point * 8 + t]     = o0;
        out[point * 8 + 4 + t] = o1;
    }
}

extern "C" void kernel_launch(void* const* d_in, const int* in_sizes, int n_in,
                              void* d_out, int out_size)
{
    const float* positions  = (const float*)d_in[0];
    const float* features   = (const float*)d_in[1];
    const float* kernel     = (const float*)d_in[2];
    const int*   neighbors  = (const int*)d_in[3];
    const int*   row_splits = (const int*)d_in[4];
    float*       out        = (float*)d_out;

    int n_pts   = in_sizes[0] / 2;
    int n_edges = in_sizes[3];
    if (n_edges > MAX_EDGES) n_edges = MAX_EDGES;

    geom_kernel<<<(n_edges + 255) / 256, 256>>>(
        (const float2*)positions, neighbors, n_edges);

    int blocks = (n_pts + PTS_PER_BLOCK - 1) / PTS_PER_BLOCK;
    rbf_layer_kernel<<<blocks, BLOCK_THREADS>>>(
        features, kernel, neighbors, row_splits, out, n_pts);
}

// round 4
// speedup vs baseline: 1.1620x; 1.1620x over previous
#include <cuda_runtime.h>
#include <math.h>

// rbfLayer, round 4: fused two-phase block-cooperative kernel.
// Phase 1: 128 threads stage per-edge decoded hat weights (wa[4], wr[4]) and
//          neighbor ids for the block's 32 points x 16 edges = 512 edges into
//          shared memory (geometry + decode computed ONCE per edge).
// Phase 2: 4 lanes/point, lane t owns feature pair j={2t,2t+1}; reads staged
//          weights via conflict-free LDS.128, gathers its 8B feature slice,
//          accumulates Z[16 nm] in f32x2, then contracts against shared K.

#define PTS_PER_BLOCK 32
#define BLOCK_THREADS 128
#define SW_PT_STRIDE 132            // 16 edges * 8 floats + 4 pad = 528 B/point

typedef unsigned long long u64;

__device__ __forceinline__ u64 pack2(float lo, float hi) {
    u64 r;
    asm("mov.b64 %0, {%1,%2};" : "=l"(r)
        : "r"(__float_as_int(lo)), "r"(__float_as_int(hi)));
    return r;
}
__device__ __forceinline__ void unpack2(u64 v, float& lo, float& hi) {
    int a, b;
    asm("mov.b64 {%0,%1}, %2;" : "=r"(a), "=r"(b) : "l"(v));
    lo = __int_as_float(a); hi = __int_as_float(b);
}
__device__ __forceinline__ u64 fma2(u64 a, u64 b, u64 c) {
    u64 d;
    asm("fma.rn.f32x2 %0, %1, %2, %3;" : "=l"(d) : "l"(a), "l"(b), "l"(c));
    return d;
}
__device__ __forceinline__ u64 mul2(u64 a, u64 b) {
    u64 d;
    asm("mul.rn.f32x2 %0, %1, %2;" : "=l"(d) : "l"(a), "l"(b));
    return d;
}

// geometry: rel -> index-space coords (s_r in [0,3), s_a in [0,4])
__device__ __forceinline__ void edge_geom(float dx, float dy,
                                          float& sr, float& sa) {
    float d2 = fmaxf(fmaf(dx, dx, dy * dy), 1e-24f);
    float rinv = rsqrtf(d2);
    sr = d2 * rinv * 1.5f;

    float ax = fabsf(dx), ay = fabsf(dy);
    float mn = fminf(ax, ay);
    float mx = fmaxf(fmaxf(ax, ay), 1e-30f);
    float tq = __fdividef(mn, mx);
    float t2 = tq * tq;
    float pl = -0.0117212f;
    pl = fmaf(pl, t2, 0.05265332f);
    pl = fmaf(pl, t2, -0.11643287f);
    pl = fmaf(pl, t2, 0.19354346f);
    pl = fmaf(pl, t2, -0.33262347f);
    pl = fmaf(pl, t2, 0.99997726f);
    float ang = pl * tq;
    if (ay > ax) ang = 1.5707963267948966f - ang;
    if (dx < 0.0f) ang = 3.141592653589793f - ang;
    float th = ang * 0.3183098861837907f;
    th = (dy < 0.0f) ? -th : th;             // [-1,1]
    sa = fmaf(th, 2.0f, 2.0f);               // [0,4]
}

// PoU hat decode: (sr, sa) -> wa[4] (angular, periodic), wr[4] (radial)
__device__ __forceinline__ void decode_w(float sr, float sa,
                                         float4& WA, float4& WR) {
    int   kr = (int)sr;
    float fr = sr - (float)kr;
    int   ka = (int)sa;
    float fa = sa - (float)ka;
    int   k0 = ka & 3;
    int   k1 = (ka + 1) & 3;

    WA.x = (k0 == 0) ? (1.0f - fa) : ((k1 == 0) ? fa : 0.0f);
    WA.y = (k0 == 1) ? (1.0f - fa) : ((k1 == 1) ? fa : 0.0f);
    WA.z = (k0 == 2) ? (1.0f - fa) : ((k1 == 2) ? fa : 0.0f);
    WA.w = (k0 == 3) ? (1.0f - fa) : ((k1 == 3) ? fa : 0.0f);

    WR.x = (kr == 0) ? (1.0f - fr) : 0.0f;
    WR.y = (kr == 1) ? (1.0f - fr) : ((kr == 0) ? fr : 0.0f);
    WR.z = (kr == 2) ? (1.0f - fr) : ((kr == 1) ? fr : 0.0f);
    WR.w = (kr == 2) ? fr : 0.0f;
}

__device__ __forceinline__ void accum16(const float4& WA, const float4& WR,
                                        u64 fv2, u64 Zp[16]) {
    u64 t0 = mul2(pack2(WA.x, WA.x), fv2);
    u64 t1 = mul2(pack2(WA.y, WA.y), fv2);
    u64 t2 = mul2(pack2(WA.z, WA.z), fv2);
    u64 t3 = mul2(pack2(WA.w, WA.w), fv2);
    u64 r0 = pack2(WR.x, WR.x);
    u64 r1 = pack2(WR.y, WR.y);
    u64 r2 = pack2(WR.z, WR.z);
    u64 r3 = pack2(WR.w, WR.w);

    Zp[0]  = fma2(r0, t0, Zp[0]);   Zp[1]  = fma2(r0, t1, Zp[1]);
    Zp[2]  = fma2(r0, t2, Zp[2]);   Zp[3]  = fma2(r0, t3, Zp[3]);
    Zp[4]  = fma2(r1, t0, Zp[4]);   Zp[5]  = fma2(r1, t1, Zp[5]);
    Zp[6]  = fma2(r1, t2, Zp[6]);   Zp[7]  = fma2(r1, t3, Zp[7]);
    Zp[8]  = fma2(r2, t0, Zp[8]);   Zp[9]  = fma2(r2, t1, Zp[9]);
    Zp[10] = fma2(r2, t2, Zp[10]);  Zp[11] = fma2(r2, t3, Zp[11]);
    Zp[12] = fma2(r3, t0, Zp[12]);  Zp[13] = fma2(r3, t1, Zp[13]);
    Zp[14] = fma2(r3, t2, Zp[14]);  Zp[15] = fma2(r3, t3, Zp[15]);
}

__global__ __launch_bounds__(BLOCK_THREADS, 8)
void rbf_layer_kernel(const float2* __restrict__ pos,
                      const float*  __restrict__ feat,
                      const float*  __restrict__ kern,   // [8][8][4][4]
                      const int*    __restrict__ nbrs,
                      const int*    __restrict__ rsp,
                      float*        __restrict__ out,
                      int n_pts, int n_edges)
{
    __shared__ float4 skp4[8 * 8 * 4];                  // 4 KB epilogue K
    __shared__ float  sw[PTS_PER_BLOCK * SW_PT_STRIDE]; // 16.5 KB staged weights
    __shared__ int4   snbr4[PTS_PER_BLOCK * 5];         // padded nbr quads

    int tid = threadIdx.x;

    // load + repack K: skp4[(i*8+nm2)*4+t] = {K[i][2t][2nm2],K[i][2t+1][2nm2],
    //                                         K[i][2t][2nm2+1],K[i][2t+1][2nm2+1]}
    for (int idx = tid; idx < 256; idx += BLOCK_THREADS) {
        int tt  = idx & 3;
        int nm2 = (idx >> 2) & 7;
        int i   = idx >> 5;
        int n0 = 2 * nm2, n1 = 2 * nm2 + 1;
        skp4[idx] = make_float4(kern[(i * 8 + 2 * tt)     * 16 + n0],
                                kern[(i * 8 + 2 * tt + 1) * 16 + n0],
                                kern[(i * 8 + 2 * tt)     * 16 + n1],
                                kern[(i * 8 + 2 * tt + 1) * 16 + n1]);
    }

    int p0   = blockIdx.x * PTS_PER_BLOCK;
    int base = __ldg(rsp + min(p0, n_pts));   // block's first edge (uniform case)

    // ---- Phase 1: stage decoded weights + nbrs for 512 block edges ----
    int nb_stage[4];
    float4 WA_s[4], WR_s[4];
    #pragma unroll
    for (int k = 0; k < 4; ++k) {
        int le = tid + k * BLOCK_THREADS;      // 0..511
        int e  = base + le;
        int pt = p0 + (le >> 4);
        bool ok = (e < n_edges) && (pt < n_pts);
        int nb = ok ? __ldg(nbrs + e) : 0;
        float2 q = __ldg(&pos[nb]);
        float2 pp = __ldg(&pos[ok ? pt : 0]);
        float sr, sa;
        edge_geom(q.x - pp.x, q.y - pp.y, sr, sa);
        decode_w(sr, sa, WA_s[k], WR_s[k]);
        nb_stage[k] = nb;
    }
    #pragma unroll
    for (int k = 0; k < 4; ++k) {
        int le = tid + k * BLOCK_THREADS;
        int pt = le >> 4, i = le & 15;
        float* dst = &sw[pt * SW_PT_STRIDE + i * 8];
        *(float4*)(dst)     = WA_s[k];
        *(float4*)(dst + 4) = WR_s[k];
        ((int*)snbr4)[pt * 20 + (i >> 2) * 4 + (i & 3)] = nb_stage[k];
    }
    __syncthreads();

    // ---- Phase 2: accumulate Z per point, 4 lanes (j-pairs) each ----
    int gid   = blockIdx.x * BLOCK_THREADS + tid;
    int point = gid >> 2;
    int t     = tid & 3;
    bool valid = (point < n_pts);
    int pclamp = valid ? point : 0;

    int beg = valid ? __ldg(rsp + pclamp)     : 0;
    int end = valid ? __ldg(rsp + pclamp + 1) : 0;
    int cnt = end - beg;
    int lpt = point - p0;
    bool staged = valid && (cnt == 16) && (beg == base + lpt * 16);

    const float2* f2 = (const float2*)feat;

    u64 Zp[16];
    #pragma unroll
    for (int k = 0; k < 16; ++k) Zp[k] = 0ull;

    if (staged) {
        const float* swp = &sw[lpt * SW_PT_STRIDE];
        #pragma unroll
        for (int i4 = 0; i4 < 4; ++i4) {
            int4 nbq = snbr4[lpt * 5 + i4];
            // batch the 4 feature gathers (MLP)
            float2 fv0 = __ldg(&f2[nbq.x * 4 + t]);
            float2 fv1 = __ldg(&f2[nbq.y * 4 + t]);
            float2 fv2v = __ldg(&f2[nbq.z * 4 + t]);
            float2 fv3 = __ldg(&f2[nbq.w * 4 + t]);
            const float* wb = swp + i4 * 32;
            float4 A0 = *(const float4*)(wb +  0), R0 = *(const float4*)(wb +  4);
            float4 A1 = *(const float4*)(wb +  8), R1 = *(const float4*)(wb + 12);
            float4 A2 = *(const float4*)(wb + 16), R2 = *(const float4*)(wb + 20);
            float4 A3 = *(const float4*)(wb + 24), R3 = *(const float4*)(wb + 28);
            accum16(A0, R0, pack2(fv0.x, fv0.y), Zp);
            accum16(A1, R1, pack2(fv1.x, fv1.y), Zp);
            accum16(A2, R2, pack2(fv2v.x, fv2v.y), Zp);
            accum16(A3, R3, pack2(fv3.x, fv3.y), Zp);
        }
    } else if (valid) {
        const float2 pp = __ldg(&pos[pclamp]);
        for (int e = beg; e < end; ++e) {
            int nb = __ldg(nbrs + e);
            float2 q = __ldg(&pos[nb]);
            float sr, sa;
            edge_geom(q.x - pp.x, q.y - pp.y, sr, sa);
            float4 WA, WR;
            decode_w(sr, sa, WA, WR);
            float2 fv = __ldg(&f2[nb * 4 + t]);
            accum16(WA, WR, pack2(fv.x, fv.y), Zp);
        }
    }

    // ---- Epilogue: pr[i] = sum_nm <K[i][jpair_t][nm], Zp[nm]>, hadd ----
    float pr[8];
    #pragma unroll
    for (int i = 0; i < 8; ++i) {
        u64 acc = 0ull;
        #pragma unroll
        for (int nm2 = 0; nm2 < 8; ++nm2) {
            float4 kk = skp4[(i * 8 + nm2) * 4 + t];
            acc = fma2(pack2(kk.x, kk.y), Zp[2 * nm2],     acc);
            acc = fma2(pack2(kk.z, kk.w), Zp[2 * nm2 + 1], acc);
        }
        float lo, hi;
        unpack2(acc, lo, hi);
        pr[i] = lo + hi;
    }

    #pragma unroll
    for (int i = 0; i < 8; ++i) {
        pr[i] += __shfl_xor_sync(0xffffffffu, pr[i], 1);
        pr[i] += __shfl_xor_sync(0xffffffffu, pr[i], 2);
    }

    if (valid) {
        float o0 = pr[0], o1 = pr[4];
        if (t == 1) { o0 = pr[1]; o1 = pr[5]; }
        if (t == 2) { o0 = pr[2]; o1 = pr[6]; }
        if (t == 3) { o0 = pr[3]; o1 = pr[7]; }
        out[point * 8 + t]     = o0;
        out[point * 8 + 4 + t] = o1;
    }
}

extern "C" void kernel_launch(void* const* d_in, const int* in_sizes, int n_in,
                              void* d_out, int out_size)
{
    const float* positions  = (const float*)d_in[0];
    const float* features   = (const float*)d_in[1];
    const float* kernel     = (const float*)d_in[2];
    const int*   neighbors  = (const int*)d_in[3];
    const int*   row_splits = (const int*)d_in[4];
    float*       out        = (float*)d_out;

    int n_pts   = in_sizes[0] / 2;
    int n_edges = in_sizes[3];

    int blocks = (n_pts + PTS_PER_BLOCK - 1) / PTS_PER_BLOCK;
    rbf_layer_kernel<<<blocks, BLOCK_THREADS>>>(
        (const float2*)positions, features, kernel, neighbors, row_splits,
        out, n_pts, n_edges);
}

// round 5
// speedup vs baseline: 1.2294x; 1.0580x over previous
#include <cuda_runtime.h>
#include <math.h>

// rbfLayer, round 5: R4 two-phase structure, latency-tuned.
//  - launch_bounds(128,5): ~102-reg budget -> no spills (R4's 64-reg cap spilled)
//  - phase-2 feature gathers batched 8-deep (MLP 8)
//  - phase-1 gathers batched across the 4 staged edges

#define PTS_PER_BLOCK 32
#define BLOCK_THREADS 128
#define SW_PT_STRIDE 132            // 16 edges * 8 floats + 4 pad

typedef unsigned long long u64;

__device__ __forceinline__ u64 pack2(float lo, float hi) {
    u64 r;
    asm("mov.b64 %0, {%1,%2};" : "=l"(r)
        : "r"(__float_as_int(lo)), "r"(__float_as_int(hi)));
    return r;
}
__device__ __forceinline__ void unpack2(u64 v, float& lo, float& hi) {
    int a, b;
    asm("mov.b64 {%0,%1}, %2;" : "=r"(a), "=r"(b) : "l"(v));
    lo = __int_as_float(a); hi = __int_as_float(b);
}
__device__ __forceinline__ u64 fma2(u64 a, u64 b, u64 c) {
    u64 d;
    asm("fma.rn.f32x2 %0, %1, %2, %3;" : "=l"(d) : "l"(a), "l"(b), "l"(c));
    return d;
}
__device__ __forceinline__ u64 mul2(u64 a, u64 b) {
    u64 d;
    asm("mul.rn.f32x2 %0, %1, %2;" : "=l"(d) : "l"(a), "l"(b));
    return d;
}

__device__ __forceinline__ void edge_geom(float dx, float dy,
                                          float& sr, float& sa) {
    float d2 = fmaxf(fmaf(dx, dx, dy * dy), 1e-24f);
    float rinv = rsqrtf(d2);
    sr = d2 * rinv * 1.5f;

    float ax = fabsf(dx), ay = fabsf(dy);
    float mn = fminf(ax, ay);
    float mx = fmaxf(fmaxf(ax, ay), 1e-30f);
    float tq = __fdividef(mn, mx);
    float t2 = tq * tq;
    float pl = -0.0117212f;
    pl = fmaf(pl, t2, 0.05265332f);
    pl = fmaf(pl, t2, -0.11643287f);
    pl = fmaf(pl, t2, 0.19354346f);
    pl = fmaf(pl, t2, -0.33262347f);
    pl = fmaf(pl, t2, 0.99997726f);
    float ang = pl * tq;
    if (ay > ax) ang = 1.5707963267948966f - ang;
    if (dx < 0.0f) ang = 3.141592653589793f - ang;
    float th = ang * 0.3183098861837907f;
    th = (dy < 0.0f) ? -th : th;
    sa = fmaf(th, 2.0f, 2.0f);
}

__device__ __forceinline__ void decode_w(float sr, float sa,
                                         float4& WA, float4& WR) {
    int   kr = (int)sr;
    float fr = sr - (float)kr;
    int   ka = (int)sa;
    float fa = sa - (float)ka;
    int   k0 = ka & 3;
    int   k1 = (ka + 1) & 3;

    WA.x = (k0 == 0) ? (1.0f - fa) : ((k1 == 0) ? fa : 0.0f);
    WA.y = (k0 == 1) ? (1.0f - fa) : ((k1 == 1) ? fa : 0.0f);
    WA.z = (k0 == 2) ? (1.0f - fa) : ((k1 == 2) ? fa : 0.0f);
    WA.w = (k0 == 3) ? (1.0f - fa) : ((k1 == 3) ? fa : 0.0f);

    WR.x = (kr == 0) ? (1.0f - fr) : 0.0f;
    WR.y = (kr == 1) ? (1.0f - fr) : ((kr == 0) ? fr : 0.0f);
    WR.z = (kr == 2) ? (1.0f - fr) : ((kr == 1) ? fr : 0.0f);
    WR.w = (kr == 2) ? fr : 0.0f;
}

__device__ __forceinline__ void accum16(const float4& WA, const float4& WR,
                                        u64 fv2, u64 Zp[16]) {
    u64 t0 = mul2(pack2(WA.x, WA.x), fv2);
    u64 t1 = mul2(pack2(WA.y, WA.y), fv2);
    u64 t2 = mul2(pack2(WA.z, WA.z), fv2);
    u64 t3 = mul2(pack2(WA.w, WA.w), fv2);
    u64 r0 = pack2(WR.x, WR.x);
    u64 r1 = pack2(WR.y, WR.y);
    u64 r2 = pack2(WR.z, WR.z);
    u64 r3 = pack2(WR.w, WR.w);

    Zp[0]  = fma2(r0, t0, Zp[0]);   Zp[1]  = fma2(r0, t1, Zp[1]);
    Zp[2]  = fma2(r0, t2, Zp[2]);   Zp[3]  = fma2(r0, t3, Zp[3]);
    Zp[4]  = fma2(r1, t0, Zp[4]);   Zp[5]  = fma2(r1, t1, Zp[5]);
    Zp[6]  = fma2(r1, t2, Zp[6]);   Zp[7]  = fma2(r1, t3, Zp[7]);
    Zp[8]  = fma2(r2, t0, Zp[8]);   Zp[9]  = fma2(r2, t1, Zp[9]);
    Zp[10] = fma2(r2, t2, Zp[10]);  Zp[11] = fma2(r2, t3, Zp[11]);
    Zp[12] = fma2(r3, t0, Zp[12]);  Zp[13] = fma2(r3, t1, Zp[13]);
    Zp[14] = fma2(r3, t2, Zp[14]);  Zp[15] = fma2(r3, t3, Zp[15]);
}

__global__ __launch_bounds__(BLOCK_THREADS, 5)
void rbf_layer_kernel(const float2* __restrict__ pos,
                      const float*  __restrict__ feat,
                      const float*  __restrict__ kern,
                      const int*    __restrict__ nbrs,
                      const int*    __restrict__ rsp,
                      float*        __restrict__ out,
                      int n_pts, int n_edges)
{
    __shared__ float4 skp4[8 * 8 * 4];
    __shared__ float  sw[PTS_PER_BLOCK * SW_PT_STRIDE];
    __shared__ int4   snbr4[PTS_PER_BLOCK * 5];

    int tid = threadIdx.x;

    for (int idx = tid; idx < 256; idx += BLOCK_THREADS) {
        int tt  = idx & 3;
        int nm2 = (idx >> 2) & 7;
        int i   = idx >> 5;
        int n0 = 2 * nm2, n1 = 2 * nm2 + 1;
        skp4[idx] = make_float4(kern[(i * 8 + 2 * tt)     * 16 + n0],
                                kern[(i * 8 + 2 * tt + 1) * 16 + n0],
                                kern[(i * 8 + 2 * tt)     * 16 + n1],
                                kern[(i * 8 + 2 * tt + 1) * 16 + n1]);
    }

    int p0   = blockIdx.x * PTS_PER_BLOCK;
    int base = __ldg(rsp + min(p0, n_pts));

    // ---- Phase 1: stage decoded weights + nbrs (loads batched 4-deep) ----
    {
        int nb_s[4];
        float2 q_s[4], pp_s[4];
        #pragma unroll
        for (int k = 0; k < 4; ++k) {
            int le = tid + k * BLOCK_THREADS;
            int e  = base + le;
            int pt = p0 + (le >> 4);
            bool ok = (e < n_edges) && (pt < n_pts);
            nb_s[k] = ok ? __ldg(nbrs + e) : 0;
        }
        #pragma unroll
        for (int k = 0; k < 4; ++k) {
            int le = tid + k * BLOCK_THREADS;
            int pt = p0 + (le >> 4);
            q_s[k]  = __ldg(&pos[nb_s[k]]);
            pp_s[k] = __ldg(&pos[(pt < n_pts) ? pt : 0]);
        }
        #pragma unroll
        for (int k = 0; k < 4; ++k) {
            int le = tid + k * BLOCK_THREADS;
            int pt = le >> 4, i = le & 15;
            float sr, sa;
            edge_geom(q_s[k].x - pp_s[k].x, q_s[k].y - pp_s[k].y, sr, sa);
            float4 WA, WR;
            decode_w(sr, sa, WA, WR);
            float* dst = &sw[pt * SW_PT_STRIDE + i * 8];
            *(float4*)(dst)     = WA;
            *(float4*)(dst + 4) = WR;
            ((int*)snbr4)[pt * 20 + (i >> 2) * 4 + (i & 3)] = nb_s[k];
        }
    }
    __syncthreads();

    // ---- Phase 2 ----
    int gid   = blockIdx.x * BLOCK_THREADS + tid;
    int point = gid >> 2;
    int t     = tid & 3;
    bool valid = (point < n_pts);
    int pclamp = valid ? point : 0;

    int beg = valid ? __ldg(rsp + pclamp)     : 0;
    int end = valid ? __ldg(rsp + pclamp + 1) : 0;
    int cnt = end - beg;
    int lpt = point - p0;
    bool staged = valid && (cnt == 16) && (beg == base + lpt * 16);

    const float2* f2 = (const float2*)feat;

    u64 Zp[16];
    #pragma unroll
    for (int k = 0; k < 16; ++k) Zp[k] = 0ull;

    if (staged) {
        const float* swp = &sw[lpt * SW_PT_STRIDE];
        // all 4 nbr quads first (4 independent LDS.128)
        int4 nbq0 = snbr4[lpt * 5 + 0];
        int4 nbq1 = snbr4[lpt * 5 + 1];
        int4 nbq2 = snbr4[lpt * 5 + 2];
        int4 nbq3 = snbr4[lpt * 5 + 3];

        #pragma unroll
        for (int h = 0; h < 2; ++h) {
            int4 a = h ? nbq2 : nbq0;
            int4 b = h ? nbq3 : nbq1;
            // 8 independent gathers in flight (MLP 8)
            float2 fv0 = __ldg(&f2[a.x * 4 + t]);
            float2 fv1 = __ldg(&f2[a.y * 4 + t]);
            float2 fv2v = __ldg(&f2[a.z * 4 + t]);
            float2 fv3 = __ldg(&f2[a.w * 4 + t]);
            float2 fv4 = __ldg(&f2[b.x * 4 + t]);
            float2 fv5 = __ldg(&f2[b.y * 4 + t]);
            float2 fv6 = __ldg(&f2[b.z * 4 + t]);
            float2 fv7 = __ldg(&f2[b.w * 4 + t]);

            const float* wb = swp + h * 64;
            float4 A0 = *(const float4*)(wb +  0), R0 = *(const float4*)(wb +  4);
            float4 A1 = *(const float4*)(wb +  8), R1 = *(const float4*)(wb + 12);
            float4 A2 = *(const float4*)(wb + 16), R2 = *(const float4*)(wb + 20);
            float4 A3 = *(const float4*)(wb + 24), R3 = *(const float4*)(wb + 28);
            accum16(A0, R0, pack2(fv0.x, fv0.y), Zp);
            accum16(A1, R1, pack2(fv1.x, fv1.y), Zp);
            accum16(A2, R2, pack2(fv2v.x, fv2v.y), Zp);
            accum16(A3, R3, pack2(fv3.x, fv3.y), Zp);
            float4 A4 = *(const float4*)(wb + 32), R4 = *(const float4*)(wb + 36);
            float4 A5 = *(const float4*)(wb + 40), R5 = *(const float4*)(wb + 44);
            float4 A6 = *(const float4*)(wb + 48), R6 = *(const float4*)(wb + 52);
            float4 A7 = *(const float4*)(wb + 56), R7 = *(const float4*)(wb + 60);
            accum16(A4, R4, pack2(fv4.x, fv4.y), Zp);
            accum16(A5, R5, pack2(fv5.x, fv5.y), Zp);
            accum16(A6, R6, pack2(fv6.x, fv6.y), Zp);
            accum16(A7, R7, pack2(fv7.x, fv7.y), Zp);
        }
    } else if (valid) {
        const float2 pp = __ldg(&pos[pclamp]);
        for (int e = beg; e < end; ++e) {
            int nb = __ldg(nbrs + e);
            float2 q = __ldg(&pos[nb]);
            float sr, sa;
            edge_geom(q.x - pp.x, q.y - pp.y, sr, sa);
            float4 WA, WR;
            decode_w(sr, sa, WA, WR);
            float2 fv = __ldg(&f2[nb * 4 + t]);
            accum16(WA, WR, pack2(fv.x, fv.y), Zp);
        }
    }

    // ---- Epilogue ----
    float pr[8];
    #pragma unroll
    for (int i = 0; i < 8; ++i) {
        u64 acc = 0ull;
        #pragma unroll
        for (int nm2 = 0; nm2 < 8; ++nm2) {
            float4 kk = skp4[(i * 8 + nm2) * 4 + t];
            acc = fma2(pack2(kk.x, kk.y), Zp[2 * nm2],     acc);
            acc = fma2(pack2(kk.z, kk.w), Zp[2 * nm2 + 1], acc);
        }
        float lo, hi;
        unpack2(acc, lo, hi);
        pr[i] = lo + hi;
    }

    #pragma unroll
    for (int i = 0; i < 8; ++i) {
        pr[i] += __shfl_xor_sync(0xffffffffu, pr[i], 1);
        pr[i] += __shfl_xor_sync(0xffffffffu, pr[i], 2);
    }

    if (valid) {
        float o0 = pr[0], o1 = pr[4];
        if (t == 1) { o0 = pr[1]; o1 = pr[5]; }
        if (t == 2) { o0 = pr[2]; o1 = pr[6]; }
        if (t == 3) { o0 = pr[3]; o1 = pr[7]; }
        out[point * 8 + t]     = o0;
        out[point * 8 + 4 + t] = o1;
    }
}

extern "C" void kernel_launch(void* const* d_in, const int* in_sizes, int n_in,
                              void* d_out, int out_size)
{
    const float* positions  = (const float*)d_in[0];
    const float* features   = (const float*)d_in[1];
    const float* kernel     = (const float*)d_in[2];
    const int*   neighbors  = (const int*)d_in[3];
    const int*   row_splits = (const int*)d_in[4];
    float*       out        = (float*)d_out;

    int n_pts   = in_sizes[0] / 2;
    int n_edges = in_sizes[3];

    int blocks = (n_pts + PTS_PER_BLOCK - 1) / PTS_PER_BLOCK;
    rbf_layer_kernel<<<blocks, BLOCK_THREADS>>>(
        (const float2*)positions, features, kernel, neighbors, row_splits,
        out, n_pts, n_edges);
}